// round 10
// baseline (speedup 1.0000x reference)
#include <cuda_runtime.h>

// YOLO loss — 2-kernel pipeline, speculative row prefetch for max MLP.
// predictions: (B<=4096, 7, 7, 2, 85) fp32
// targets_boxes: (B, 20, 4) fp32 ; targets_labels: (B, 20) int32
// out: scalar fp32
//
// g_win encoding: 0 = no object (zero-initialized at module load, and
// restored to 0 by k_cell after each use). Otherwise value v in [1,20]
// means winner box index w = NBOX - v (atomicMax of NBOX-n == min n).

#define S_GRID 7
#define NB 2
#define NC 80
#define NBOX 20
#define CELLS (S_GRID * S_GRID)
#define ROW 85
#define THREADS 256
#define NWARPS (THREADS / 32)
#define FULLMASK 0xffffffffu
#define MAX_B 4096

__device__ int g_win[MAX_B * CELLS];   // 0 = none; else NBOX - box_index

// ---------------- encode: one thread per (image, box); also zeroes out ----
__global__ __launch_bounds__(THREADS)
void k_encode(const float* __restrict__ boxes, float* out, int total_tb)
{
    int i = blockIdx.x * THREADS + threadIdx.x;
    if (i == 0) *out = 0.0f;
    if (i >= total_tb) return;
    const int b = i / NBOX;
    const int n = i - b * NBOX;
    const float4 bb = *reinterpret_cast<const float4*>(boxes + (size_t)i * 4);
    float x = (bb.x + bb.z) * 0.5f;
    float y = (bb.y + bb.w) * 0.5f;
    int jb = min(max((int)floorf(x * (float)S_GRID), 0), S_GRID - 1);
    int ib = min(max((int)floorf(y * (float)S_GRID), 0), S_GRID - 1);
    atomicMax(&g_win[b * CELLS + ib * S_GRID + jb], NBOX - n);
}

// ---------------- everything else: one thread per cell ----------------
__global__ __launch_bounds__(THREADS)
void k_cell(const float* __restrict__ pred,
            const float* __restrict__ boxes,
            const int*   __restrict__ labels,
            float* __restrict__ out,
            int total_cells, float inv_B)
{
    const int tid  = threadIdx.x;
    const int lane = tid & 31;
    const int wib  = tid >> 5;
    const int cg   = blockIdx.x * THREADS + tid;

    float acc = 0.0f;
    bool  isobj = false;
    int   offset = 0, lbl = 0;

    if (cg < total_cells) {
        const float* prow = pred + (size_t)cg * (NB * ROW);

        // ---- speculative prefetch: win value + both boxes' 5 floats.
        // 11 independent loads issued before any branch. Box0's 5 floats
        // share the sector with its conf; box1 costs one extra sector.
        const int v = g_win[cg];
        float p0[5], p1[5];
        #pragma unroll
        for (int k = 0; k < 5; k++) p0[k] = __ldcs(prow + k);
        #pragma unroll
        for (int k = 0; k < 5; k++) p1[k] = __ldcs(prow + ROW + k);

        if (v == 0) {
            // no-object: both boxes' confidence only
            acc = 0.5f * (p0[4] * p0[4] + p1[4] * p1[4]);   // LAMBDA_NOOBJ
        } else {
            g_win[cg] = 0;                         // restore zeroed invariant
            const int w    = NBOX - v;             // winner box index
            const int b    = cg / CELLS;
            const int cidx = cg - b * CELLS;
            const int ci   = cidx / S_GRID;
            const int cj   = cidx - ci * S_GRID;

            // recompute target from winning box (its clipped cell == this cell)
            const float4 bb = *reinterpret_cast<const float4*>(
                boxes + ((size_t)b * NBOX + w) * 4);
            lbl = labels[(size_t)b * NBOX + w];
            const float x  = (bb.x + bb.z) * 0.5f;
            const float y  = (bb.y + bb.w) * 0.5f;
            const float tw = bb.z - bb.x;
            const float th = bb.w - bb.y;
            const float tx = x * (float)S_GRID - (float)cj;
            const float ty = y * (float)S_GRID - (float)ci;

            const float bx1 = tx - tw * 0.5f, by1 = ty - th * 0.5f;
            const float bx2 = tx + tw * 0.5f, by2 = ty + th * 0.5f;
            const float barea = (bx2 - bx1) * (by2 - by1);

            float iou[2];
            #pragma unroll
            for (int bxi = 0; bxi < 2; bxi++) {
                const float* p = bxi ? p1 : p0;
                float ax1 = p[0] - p[2] * 0.5f, ay1 = p[1] - p[3] * 0.5f;
                float ax2 = p[0] + p[2] * 0.5f, ay2 = p[1] + p[3] * 0.5f;
                float iw = fmaxf(fminf(ax2, bx2) - fmaxf(ax1, bx1), 0.0f);
                float ih = fmaxf(fminf(ay2, by2) - fmaxf(ay1, by1), 0.0f);
                float inter = iw * ih;
                float uni = (ax2 - ax1) * (ay2 - ay1) + barea - inter;
                iou[bxi] = inter / (uni + 1e-6f);
            }
            const int best = (iou[1] > iou[0]) ? 1 : 0;   // first max wins
            const float* p = best ? p1 : p0;

            float dx = p[0] - tx, dy = p[1] - ty;
            acc += 5.0f * (dx * dx + dy * dy);                    // coord xy
            float sw = sqrtf(fmaxf(p[2], 1e-6f)) - sqrtf(fmaxf(tw, 1e-6f));
            float sh = sqrtf(fmaxf(p[3], 1e-6f)) - sqrtf(fmaxf(th, 1e-6f));
            acc += 5.0f * (sw * sw + sh * sh);                    // coord wh
            float dc = p[4] - 1.0f;
            acc += dc * dc;                                       // conf obj

            isobj  = true;
            offset = cg * (NB * ROW) + best * ROW + 5;
        }
    }

    // ---- class loss: warp-cooperative over this warp's obj cells ----
    unsigned m = __ballot_sync(FULLMASK, isobj);
    while (m) {
        const int l = __ffs(m) - 1;
        m &= m - 1;
        const int off = __shfl_sync(FULLMASK, offset, l);
        const int lb  = __shfl_sync(FULLMASK, lbl, l);
        #pragma unroll
        for (int cc = lane; cc < NC; cc += 32) {
            float d = __ldcs(pred + off + cc) - ((cc == lb) ? 1.0f : 0.0f);
            acc += d * d;
        }
    }

    // ---- block reduce + one atomic ----
    #pragma unroll
    for (int off = 16; off > 0; off >>= 1)
        acc += __shfl_down_sync(FULLMASK, acc, off);
    __shared__ float wsum[NWARPS];
    if (lane == 0) wsum[wib] = acc;
    __syncthreads();
    if (wib == 0) {
        float s = (lane < NWARPS) ? wsum[lane] : 0.0f;
        #pragma unroll
        for (int off = NWARPS / 2; off > 0; off >>= 1)
            s += __shfl_down_sync(FULLMASK, s, off);
        if (lane == 0) atomicAdd(out, s * inv_B);
    }
}

extern "C" void kernel_launch(void* const* d_in, const int* in_sizes, int n_in,
                              void* d_out, int out_size)
{
    const float* pred   = (const float*)d_in[0];
    const float* boxes  = (const float*)d_in[1];
    const int*   labels = (const int*)d_in[2];
    float* out = (float*)d_out;

    const int B = in_sizes[0] / (CELLS * NB * ROW);
    const int total_cells = B * CELLS;
    const int total_tb    = B * NBOX;
    const float inv_B = 1.0f / (float)B;

    const int gb_cells = (total_cells + THREADS - 1) / THREADS;
    const int gb_tb    = (total_tb + THREADS - 1) / THREADS;

    k_encode<<<gb_tb,    THREADS>>>(boxes, out, total_tb);
    k_cell  <<<gb_cells, THREADS>>>(pred, boxes, labels, out,
                                    total_cells, inv_B);
}

// round 13
// speedup vs baseline: 1.2973x; 1.2973x over previous
#include <cuda_runtime.h>

// YOLO loss — 2-kernel pipeline; class loss batched 4-wide for MLP.
// predictions: (B<=4096, 7, 7, 2, 85) fp32
// targets_boxes: (B, 20, 4) fp32 ; targets_labels: (B, 20) int32
// out: scalar fp32
//
// g_win encoding: 0 = no object (zero-initialized at module load, and
// restored to 0 by k_cell after each use). Otherwise value v in [1,20]
// means winner box index w = NBOX - v (atomicMax of NBOX-n == min n).

#define S_GRID 7
#define NB 2
#define NC 80
#define NBOX 20
#define CELLS (S_GRID * S_GRID)
#define ROW 85
#define THREADS 256
#define NWARPS (THREADS / 32)
#define FULLMASK 0xffffffffu
#define MAX_B 4096

__device__ int g_win[MAX_B * CELLS];   // 0 = none; else NBOX - box_index

// ---------------- encode: one thread per (image, box); also zeroes out ----
__global__ __launch_bounds__(THREADS)
void k_encode(const float* __restrict__ boxes, float* out, int total_tb)
{
    int i = blockIdx.x * THREADS + threadIdx.x;
    if (i == 0) *out = 0.0f;
    if (i >= total_tb) return;
    const int b = i / NBOX;
    const int n = i - b * NBOX;
    const float4 bb = *reinterpret_cast<const float4*>(boxes + (size_t)i * 4);
    float x = (bb.x + bb.z) * 0.5f;
    float y = (bb.y + bb.w) * 0.5f;
    int jb = min(max((int)floorf(x * (float)S_GRID), 0), S_GRID - 1);
    int ib = min(max((int)floorf(y * (float)S_GRID), 0), S_GRID - 1);
    atomicMax(&g_win[b * CELLS + ib * S_GRID + jb], NBOX - n);
}

// ---------------- everything else: one thread per cell ----------------
__global__ __launch_bounds__(THREADS)
void k_cell(const float* __restrict__ pred,
            const float* __restrict__ boxes,
            const int*   __restrict__ labels,
            float* __restrict__ out,
            int total_cells, float inv_B)
{
    const int tid  = threadIdx.x;
    const int lane = tid & 31;
    const int wib  = tid >> 5;
    const int cg   = blockIdx.x * THREADS + tid;

    float acc = 0.0f;
    bool  isobj = false;
    int   offset = 0, lbl = 0;

    if (cg < total_cells) {
        const int v = g_win[cg];
        const float* prow = pred + (size_t)cg * (NB * ROW);

        if (v == 0) {
            float c0 = __ldcs(prow + 4);
            float c1 = __ldcs(prow + ROW + 4);
            acc = 0.5f * (c0 * c0 + c1 * c1);          // LAMBDA_NOOBJ
        } else {
            g_win[cg] = 0;                         // restore zeroed invariant
            const int w    = NBOX - v;             // winner box index
            const int b    = cg / CELLS;
            const int cidx = cg - b * CELLS;
            const int ci   = cidx / S_GRID;
            const int cj   = cidx - ci * S_GRID;

            const float4 bb = *reinterpret_cast<const float4*>(
                boxes + ((size_t)b * NBOX + w) * 4);
            lbl = labels[(size_t)b * NBOX + w];
            const float x  = (bb.x + bb.z) * 0.5f;
            const float y  = (bb.y + bb.w) * 0.5f;
            const float tw = bb.z - bb.x;
            const float th = bb.w - bb.y;
            const float tx = x * (float)S_GRID - (float)cj;
            const float ty = y * (float)S_GRID - (float)ci;

            float p0[5], p1[5];
            #pragma unroll
            for (int k = 0; k < 5; k++) p0[k] = __ldcs(prow + k);
            #pragma unroll
            for (int k = 0; k < 5; k++) p1[k] = __ldcs(prow + ROW + k);

            const float bx1 = tx - tw * 0.5f, by1 = ty - th * 0.5f;
            const float bx2 = tx + tw * 0.5f, by2 = ty + th * 0.5f;
            const float barea = (bx2 - bx1) * (by2 - by1);

            float iou[2];
            #pragma unroll
            for (int bxi = 0; bxi < 2; bxi++) {
                const float* p = bxi ? p1 : p0;
                float ax1 = p[0] - p[2] * 0.5f, ay1 = p[1] - p[3] * 0.5f;
                float ax2 = p[0] + p[2] * 0.5f, ay2 = p[1] + p[3] * 0.5f;
                float iw = fmaxf(fminf(ax2, bx2) - fmaxf(ax1, bx1), 0.0f);
                float ih = fmaxf(fminf(ay2, by2) - fmaxf(ay1, by1), 0.0f);
                float inter = iw * ih;
                float uni = (ax2 - ax1) * (ay2 - ay1) + barea - inter;
                iou[bxi] = inter / (uni + 1e-6f);
            }
            const int best = (iou[1] > iou[0]) ? 1 : 0;   // first max wins
            const float* p = best ? p1 : p0;

            float dx = p[0] - tx, dy = p[1] - ty;
            acc += 5.0f * (dx * dx + dy * dy);                    // coord xy
            float sw = sqrtf(fmaxf(p[2], 1e-6f)) - sqrtf(fmaxf(tw, 1e-6f));
            float sh = sqrtf(fmaxf(p[3], 1e-6f)) - sqrtf(fmaxf(th, 1e-6f));
            acc += 5.0f * (sw * sw + sh * sh);                    // coord wh
            float dc = p[4] - 1.0f;
            acc += dc * dc;                                       // conf obj

            isobj  = true;
            offset = cg * (NB * ROW) + best * ROW + 5;
        }
    }

    // ---- class loss: warp-cooperative, batched 4 cells per stall ----
    // per lane the three class columns: lane, lane+32, lane+64 (last only lane<16)
    const int cc0 = lane, cc1 = lane + 32, cc2 = lane + 64;
    const bool has2 = (lane < NC - 64);
    float accb = 0.0f;

    unsigned m = __ballot_sync(FULLMASK, isobj);
    while (__popc(m) >= 4) {
        int l0 = __ffs(m) - 1; m &= m - 1;
        int l1 = __ffs(m) - 1; m &= m - 1;
        int l2 = __ffs(m) - 1; m &= m - 1;
        int l3 = __ffs(m) - 1; m &= m - 1;
        int o0 = __shfl_sync(FULLMASK, offset, l0), b0 = __shfl_sync(FULLMASK, lbl, l0);
        int o1 = __shfl_sync(FULLMASK, offset, l1), b1 = __shfl_sync(FULLMASK, lbl, l1);
        int o2 = __shfl_sync(FULLMASK, offset, l2), b2 = __shfl_sync(FULLMASK, lbl, l2);
        int o3 = __shfl_sync(FULLMASK, offset, l3), b3 = __shfl_sync(FULLMASK, lbl, l3);
        // 12 independent loads, then accumulate
        float t00 = __ldcs(pred + o0 + cc0), t01 = __ldcs(pred + o0 + cc1);
        float t10 = __ldcs(pred + o1 + cc0), t11 = __ldcs(pred + o1 + cc1);
        float t20 = __ldcs(pred + o2 + cc0), t21 = __ldcs(pred + o2 + cc1);
        float t30 = __ldcs(pred + o3 + cc0), t31 = __ldcs(pred + o3 + cc1);
        float t02 = has2 ? __ldcs(pred + o0 + cc2) : 0.0f;
        float t12 = has2 ? __ldcs(pred + o1 + cc2) : 0.0f;
        float t22 = has2 ? __ldcs(pred + o2 + cc2) : 0.0f;
        float t32 = has2 ? __ldcs(pred + o3 + cc2) : 0.0f;
        float d;
        d = t00 - (cc0 == b0 ? 1.f : 0.f); acc  += d * d;
        d = t01 - (cc1 == b0 ? 1.f : 0.f); accb += d * d;
        d = t10 - (cc0 == b1 ? 1.f : 0.f); acc  += d * d;
        d = t11 - (cc1 == b1 ? 1.f : 0.f); accb += d * d;
        d = t20 - (cc0 == b2 ? 1.f : 0.f); acc  += d * d;
        d = t21 - (cc1 == b2 ? 1.f : 0.f); accb += d * d;
        d = t30 - (cc0 == b3 ? 1.f : 0.f); acc  += d * d;
        d = t31 - (cc1 == b3 ? 1.f : 0.f); accb += d * d;
        if (has2) {
            d = t02 - (cc2 == b0 ? 1.f : 0.f); acc  += d * d;
            d = t12 - (cc2 == b1 ? 1.f : 0.f); accb += d * d;
            d = t22 - (cc2 == b2 ? 1.f : 0.f); acc  += d * d;
            d = t32 - (cc2 == b3 ? 1.f : 0.f); accb += d * d;
        }
    }
    while (m) {
        int l0 = __ffs(m) - 1; m &= m - 1;
        int o0 = __shfl_sync(FULLMASK, offset, l0), b0 = __shfl_sync(FULLMASK, lbl, l0);
        float t00 = __ldcs(pred + o0 + cc0);
        float t01 = __ldcs(pred + o0 + cc1);
        float t02 = has2 ? __ldcs(pred + o0 + cc2) : 0.0f;
        float d;
        d = t00 - (cc0 == b0 ? 1.f : 0.f); acc  += d * d;
        d = t01 - (cc1 == b0 ? 1.f : 0.f); accb += d * d;
        if (has2) { d = t02 - (cc2 == b0 ? 1.f : 0.f); acc += d * d; }
    }
    acc += accb;

    // ---- block reduce + one atomic ----
    #pragma unroll
    for (int off = 16; off > 0; off >>= 1)
        acc += __shfl_down_sync(FULLMASK, acc, off);
    __shared__ float wsum[NWARPS];
    if (lane == 0) wsum[wib] = acc;
    __syncthreads();
    if (wib == 0) {
        float s = (lane < NWARPS) ? wsum[lane] : 0.0f;
        #pragma unroll
        for (int off = NWARPS / 2; off > 0; off >>= 1)
            s += __shfl_down_sync(FULLMASK, s, off);
        if (lane == 0) atomicAdd(out, s * inv_B);
    }
}

extern "C" void kernel_launch(void* const* d_in, const int* in_sizes, int n_in,
                              void* d_out, int out_size)
{
    const float* pred   = (const float*)d_in[0];
    const float* boxes  = (const float*)d_in[1];
    const int*   labels = (const int*)d_in[2];
    float* out = (float*)d_out;

    const int B = in_sizes[0] / (CELLS * NB * ROW);
    const int total_cells = B * CELLS;
    const int total_tb    = B * NBOX;
    const float inv_B = 1.0f / (float)B;

    const int gb_cells = (total_cells + THREADS - 1) / THREADS;
    const int gb_tb    = (total_tb + THREADS - 1) / THREADS;

    k_encode<<<gb_tb,    THREADS>>>(boxes, out, total_tb);
    k_cell  <<<gb_cells, THREADS>>>(pred, boxes, labels, out,
                                    total_cells, inv_B);
}